// round 6
// baseline (speedup 1.0000x reference)
#include <cuda_runtime.h>
#include <cuda_bf16.h>
#include <cstdint>

#define NB 8192
#define NM 6
#define NH 256
#define NT 30
#define OL 20
#define NI 40        // 2*OL
#define NK 296       // NI + NH
#define KP 320       // K padded (10 chunks of 32)
#define NC 10
#define NG 1024      // 4*NH
#define ROWS (NM*NB) // 49152
#define HIST_T (NT+OL)

// smem: per stage 4 matrices (Ah,Al,Bh,Bl), each 128 rows x 32 bf16, row stride 80B
#define STRIDE 80
#define MATB (128*STRIDE)      // 10240
#define ST (4*MATB)            // 40960
#define NSTAGE 3
#define SMEM_TOTAL (NSTAGE*ST) // 122880

// ---------------- device state ----------------
__device__ __align__(16) __nv_bfloat16 g_Ah[2][(size_t)ROWS*KP];
__device__ __align__(16) __nv_bfloat16 g_Al[2][(size_t)ROWS*KP];
__device__ __align__(16) __nv_bfloat16 g_Bh[(size_t)NG*KP];
__device__ __align__(16) __nv_bfloat16 g_Bl[(size_t)NG*KP];
__device__ __align__(16) float g_c[(size_t)ROWS*NH];
__device__ __align__(16) float g_hist[(size_t)NM*HIST_T*NB*2];
__device__ __align__(16) unsigned char g_mask8[(size_t)ROWS*5];  // masks for the NEXT relse step
__device__ __align__(16) float g_bias[NG];

// ---------------- helpers ----------------
__device__ __forceinline__ uint32_t smem_u32(const void* p){
    uint32_t a;
    asm("{ .reg .u64 t; cvta.to.shared.u64 t, %1; cvt.u32.u64 %0, t; }" : "=r"(a) : "l"(p));
    return a;
}
__device__ __forceinline__ void cp16(uint32_t dst, const void* src){
    asm volatile("cp.async.cg.shared.global [%0], [%1], 16;" :: "r"(dst), "l"(src));
}
__device__ __forceinline__ void ldsm4(uint32_t* r, uint32_t addr){
    asm volatile("ldmatrix.sync.aligned.m8n8.x4.shared.b16 {%0,%1,%2,%3}, [%4];"
        : "=r"(r[0]),"=r"(r[1]),"=r"(r[2]),"=r"(r[3]) : "r"(addr));
}
__device__ __forceinline__ void mma_bf16(float* d, const uint32_t* a, const uint32_t* b){
    asm volatile("mma.sync.aligned.m16n8k16.row.col.f32.bf16.bf16.f32 "
        "{%0,%1,%2,%3}, {%4,%5,%6,%7}, {%8,%9}, {%0,%1,%2,%3};"
        : "+f"(d[0]),"+f"(d[1]),"+f"(d[2]),"+f"(d[3])
        : "r"(a[0]),"r"(a[1]),"r"(a[2]),"r"(a[3]), "r"(b[0]),"r"(b[1]));
}
__device__ __forceinline__ void bf16_split(float x, __nv_bfloat16 &hi, __nv_bfloat16 &lo){
    hi = __float2bfloat16(x);
    lo = __float2bfloat16(x - __bfloat162float(hi));
}

// ---------------- threefry-2x32-20 (JAX partitionable) ----------------
__device__ __forceinline__ void tfr(unsigned &x0, unsigned &x1, int r){
    x0 += x1; x1 = __funnelshift_l(x1, x1, r); x1 ^= x0;
}
__device__ __forceinline__ uint2 threefry2x32(unsigned k0, unsigned k1, unsigned c0, unsigned c1){
    unsigned k2 = k0 ^ k1 ^ 0x1BD11BDAu;
    unsigned x0 = c0 + k0, x1 = c1 + k1;
    tfr(x0,x1,13); tfr(x0,x1,15); tfr(x0,x1,26); tfr(x0,x1, 6);
    x0 += k1; x1 += k2 + 1u;
    tfr(x0,x1,17); tfr(x0,x1,29); tfr(x0,x1,16); tfr(x0,x1,24);
    x0 += k2; x1 += k0 + 2u;
    tfr(x0,x1,13); tfr(x0,x1,15); tfr(x0,x1,26); tfr(x0,x1, 6);
    x0 += k0; x1 += k1 + 3u;
    tfr(x0,x1,17); tfr(x0,x1,29); tfr(x0,x1,16); tfr(x0,x1,24);
    x0 += k1; x1 += k2 + 4u;
    tfr(x0,x1,13); tfr(x0,x1,15); tfr(x0,x1,26); tfr(x0,x1, 6);
    x0 += k2; x1 += k0 + 5u;
    return make_uint2(x0, x1);
}

// One mask byte = 8 dropout keep-bits for (row, j-octet) at step t.
__device__ __forceinline__ void mask_unit(int flat, int t){
    int row = flat / 5, oct = flat % 5;
    int m = row >> 13, b = row & (NB-1);
    uint2 key = threefry2x32(0u, 42u, 0u, (unsigned)(m*NT + t));
    unsigned base = (unsigned)b*NI + (unsigned)oct*8u;
    unsigned byte = 0;
    #pragma unroll
    for (int j = 0; j < 8; j++){
        uint2 r = threefry2x32(key.x, key.y, 0u, base + (unsigned)j);
        if ((r.x ^ r.y) < 0xC0000000u) byte |= (1u << j);
    }
    g_mask8[flat] = (unsigned char)byte;
}

// Pack weights transposed+split: B[n][k], n = h*4+gate (i,f,g,o)
__global__ void pack_weights(const float* __restrict__ W_ih, const float* __restrict__ W_hh,
                             const float* __restrict__ b_ih, const float* __restrict__ b_hh){
    int idx = blockIdx.x*blockDim.x + threadIdx.x;
    if (idx < NG*KP){
        int k = idx % KP, n = idx / KP;
        int h = n >> 2, g = n & 3;
        int col = g*NH + h;
        float w = 0.f;
        if (k < NI)       w = W_ih[col*NI + k];
        else if (k < NK)  w = W_hh[col*NH + (k - NI)];
        __nv_bfloat16 hi, lo;
        bf16_split(w, hi, lo);
        g_Bh[idx] = hi;
        g_Bl[idx] = lo;
    }
    if (idx < NG){
        int h = idx >> 2, g = idx & 3;
        int col = g*NH + h;
        g_bias[idx] = b_ih[col] + b_hh[col];
    }
}

__global__ void init_state(const float* __restrict__ h0, const float* __restrict__ c0,
                           const float* __restrict__ traj){
    int idx = blockIdx.x*blockDim.x + threadIdx.x;
    if (idx < ROWS*NH){
        int h = idx % NH, row = idx / NH;
        int b = row % NB;
        float hv = h0[(size_t)b*NH + h];
        __nv_bfloat16 hi, lo;
        bf16_split(hv, hi, lo);
        size_t a = (size_t)row*KP + NI + h;
        g_Ah[0][a] = hi;
        g_Al[0][a] = lo;
        g_c[idx] = c0[idx];
    }
    if (idx < ROWS*(KP-NK)){   // zero K padding, both parities
        int p = idx % (KP-NK), row = idx / (KP-NK);
        size_t a = (size_t)row*KP + NK + p;
        g_Ah[0][a] = __float2bfloat16(0.f); g_Al[0][a] = __float2bfloat16(0.f);
        g_Ah[1][a] = __float2bfloat16(0.f); g_Al[1][a] = __float2bfloat16(0.f);
    }
    if (idx < NM*OL*NB*2){
        int dd = idx & 1;
        int rest = idx >> 1;
        int b = rest % NB; rest /= NB;
        int s = rest % OL;
        int m = rest / OL;
        g_hist[(((size_t)m*HIST_T + s)*NB + b)*2 + dd] = traj[((size_t)s*NB + b)*2 + dd];
    }
    if (idx < ROWS*5) mask_unit(idx, 0);   // dropout masks for step 0
}

// rel head (reads split h of parity hp_idx) + spatial embed/dropout writing
// split x into parity (t_se&1). One warp per (mode,batch) row.
__global__ void relse_kernel(const float* __restrict__ W_pred, const float* __restrict__ b_pred,
                             const float* __restrict__ W_se,  const float* __restrict__ b_se,
                             float* __restrict__ out, int t_out, int t_se, int hp_idx){
    __shared__ float sW[NI*41];
    __shared__ float sb[NI];
    __shared__ float swin[8][NI];
    int tid = threadIdx.x;
    int lane = tid & 31;
    int w = tid >> 5;
    for (int i = tid; i < NI*NI; i += blockDim.x){
        int j = i / NI, k = i % NI;
        sW[j*41 + k] = W_se[i];
    }
    if (tid < NI) sb[tid] = b_se[tid];
    __syncthreads();

    int row = blockIdx.x*8 + w;
    int m = row >> 13;
    int b = row & (NB-1);

    float rel0 = 0.f, rel1 = 0.f;
    if (t_out >= 0){
        const __nv_bfloat16* hh = g_Ah[hp_idx] + (size_t)row*KP + NI;
        const __nv_bfloat16* hl = g_Al[hp_idx] + (size_t)row*KP + NI;
        const float* wp = W_pred + (size_t)m*2*NH;
        float p0 = 0.f, p1 = 0.f;
        #pragma unroll
        for (int k = lane; k < NH; k += 32){
            float hv = __bfloat162float(hh[k]) + __bfloat162float(hl[k]);
            p0 = fmaf(hv, wp[k],      p0);
            p1 = fmaf(hv, wp[NH + k], p1);
        }
        #pragma unroll
        for (int off = 16; off; off >>= 1){
            p0 += __shfl_xor_sync(0xffffffffu, p0, off);
            p1 += __shfl_xor_sync(0xffffffffu, p1, off);
        }
        rel0 = p0 + b_pred[m*2 + 0];
        rel1 = p1 + b_pred[m*2 + 1];
        if (lane == 0){
            int s = t_out + OL;
            float* hp = g_hist + (((size_t)m*HIST_T + s)*NB + b)*2;
            hp[0] = rel0; hp[1] = rel1;
            float* op = out + (((size_t)b*NM + m)*NT + t_out)*2;
            op[0] = rel0; op[1] = rel1;
        }
    }

    if (t_se < NT){
        for (int k = lane; k < NI; k += 32){
            int q = k >> 1, d = k & 1;
            swin[w][k] = g_hist[(((size_t)m*HIST_T + (t_se + q))*NB + b)*2 + d];
        }
        __syncwarp();
        if (t_out >= 0 && lane == 0){
            swin[w][NI-2] = rel0;
            swin[w][NI-1] = rel1;
        }
        __syncwarp();
        int xp = t_se & 1;
        __nv_bfloat16* xh = g_Ah[xp] + (size_t)row*KP;
        __nv_bfloat16* xl = g_Al[xp] + (size_t)row*KP;
        for (int j = lane; j < NI; j += 32){
            float acc = sb[j];
            const float* wr = sW + j*41;
            #pragma unroll 8
            for (int k = 0; k < NI; k++) acc = fmaf(swin[w][k], wr[k], acc);
            acc = acc > 0.f ? acc : 0.01f*acc;
            unsigned keep = (g_mask8[row*5 + (j >> 3)] >> (j & 7)) & 1u;
            acc = keep ? acc*(1.0f/0.75f) : 0.f;
            __nv_bfloat16 hi, lo;
            bf16_split(acc, hi, lo);
            xh[j] = hi;
            xl[j] = lo;
        }
    }
}

// bf16x3 mma.sync GEMM + fused LSTM cell + mask gen for step t_next.
// CTA tile 128(M)x128(N). 8 warps: warp_m = wid&1 (64 rows), warp_n = wid>>1 (32 cols).
// 3-stage cp.async pipeline, one __syncthreads per K chunk.
__global__ __launch_bounds__(256, 1) void lstm_mma_kernel(int pin, int t_next){
    extern __shared__ __align__(128) char smem[];
    const int tid = threadIdx.x;
    const int wid = tid >> 5, lane = tid & 31;
    const int wm = wid & 1, wn = wid >> 1;
    const int r0 = blockIdx.y * 128;
    const int n0 = blockIdx.x * 128;
    const uint32_t sb = smem_u32(smem);

    const __nv_bfloat16* Ah = g_Ah[pin];
    const __nv_bfloat16* Al = g_Al[pin];
    __nv_bfloat16* Aho = g_Ah[pin ^ 1];
    __nv_bfloat16* Alo = g_Al[pin ^ 1];

    float acc[4][4][4];
    #pragma unroll
    for (int i = 0; i < 4; i++)
        #pragma unroll
        for (int j = 0; j < 4; j++)
            #pragma unroll
            for (int q = 0; q < 4; q++) acc[i][j][q] = 0.f;

    auto load_stage = [&](int c){
        uint32_t base = sb + (c % NSTAGE)*ST;
        #pragma unroll
        for (int i = 0; i < 8; i++){
            int v = i*256 + tid;
            int mat = v >> 9;            // 0:Ah 1:Al 2:Bh 3:Bl
            int rr  = (v >> 2) & 127;
            int seg = v & 3;
            uint32_t dst = base + mat*MATB + rr*STRIDE + seg*16;
            const __nv_bfloat16* src;
            size_t off = (size_t)(c*32 + seg*8);
            if      (mat == 0) src = Ah   + (size_t)(r0 + rr)*KP + off;
            else if (mat == 1) src = Al   + (size_t)(r0 + rr)*KP + off;
            else if (mat == 2) src = g_Bh + (size_t)(n0 + rr)*KP + off;
            else               src = g_Bl + (size_t)(n0 + rr)*KP + off;
            cp16(dst, src);
        }
        asm volatile("cp.async.commit_group;" ::: "memory");
    };

    // ldmatrix per-lane address offsets
    const int l7 = lane & 7, mi = lane >> 3;
    const uint32_t a_off = (uint32_t)((l7 + ((mi & 1) << 3))*STRIDE + ((mi >> 1) << 4));
    const uint32_t b_off = (uint32_t)((l7 + ((mi >> 1) << 3))*STRIDE + ((mi & 1) << 4));

    load_stage(0);
    load_stage(1);

    // Dropout-mask generation for the NEXT step, hidden in the DMA shadow /
    // mainloop stall slack. 245760 byte-units over 786432 threads.
    {
        int flat = (blockIdx.y*gridDim.x + blockIdx.x)*blockDim.x + tid;
        if (t_next < NT && flat < ROWS*5) mask_unit(flat, t_next);
    }

    for (int c = 0; c < NC; c++){
        asm volatile("cp.async.wait_group 1;" ::: "memory");
        __syncthreads();
        if (c + 2 < NC) load_stage(c + 2);
        else if (c + 2 == NC) asm volatile("cp.async.commit_group;" ::: "memory"); // keep group count in step
        uint32_t base = sb + (c % NSTAGE)*ST;
        uint32_t As  = base           + wm*64*STRIDE;
        uint32_t Als = base + MATB    + wm*64*STRIDE;
        uint32_t Bs  = base + 2*MATB  + wn*32*STRIDE;
        uint32_t Bls = base + 3*MATB  + wn*32*STRIDE;
        const int ks_end = (c == NC-1) ? 1 : 2;   // chunk 9: K 288..303 real (+pad), 304..319 all pad
        for (int ks = 0; ks < ks_end; ks++){
            uint32_t kb = ks*32;
            uint32_t ah[4][4], al[4][4], bh[4][2], bl[4][2];
            #pragma unroll
            for (int mt = 0; mt < 4; mt++){
                ldsm4(ah[mt], As  + mt*16*STRIDE + kb + a_off);
                ldsm4(al[mt], Als + mt*16*STRIDE + kb + a_off);
            }
            #pragma unroll
            for (int bt = 0; bt < 2; bt++){
                uint32_t t4[4];
                ldsm4(t4, Bs + bt*16*STRIDE + kb + b_off);
                bh[2*bt][0] = t4[0]; bh[2*bt][1] = t4[1];
                bh[2*bt+1][0] = t4[2]; bh[2*bt+1][1] = t4[3];
                ldsm4(t4, Bls + bt*16*STRIDE + kb + b_off);
                bl[2*bt][0] = t4[0]; bl[2*bt][1] = t4[1];
                bl[2*bt+1][0] = t4[2]; bl[2*bt+1][1] = t4[3];
            }
            #pragma unroll
            for (int mt = 0; mt < 4; mt++)
                #pragma unroll
                for (int nt = 0; nt < 4; nt++){
                    mma_bf16(acc[mt][nt], ah[mt], bh[nt]);
                    mma_bf16(acc[mt][nt], ah[mt], bl[nt]);
                    mma_bf16(acc[mt][nt], al[mt], bh[nt]);
                }
        }
    }

    // Epilogue: fragment (mt,nt): thread owns rows r_l, r_l+8; cols 2*quad, +1.
    const int quad = lane & 3, r_l = lane >> 2;
    #pragma unroll
    for (int mt = 0; mt < 4; mt++)
        #pragma unroll
        for (int nt = 0; nt < 4; nt++){
            float* d = acc[mt][nt];
            int nb = n0 + wn*32 + nt*8 + 2*quad;
            float b0 = g_bias[nb], b1 = g_bias[nb + 1];
            d[0] += b0; d[1] += b1; d[2] += b0; d[3] += b1;
            float e0 = __shfl_xor_sync(0xffffffffu, d[0], 1);
            float e1 = __shfl_xor_sync(0xffffffffu, d[1], 1);
            float e2 = __shfl_xor_sync(0xffffffffu, d[2], 1);
            float e3 = __shfl_xor_sync(0xffffffffu, d[3], 1);
            if (!(quad & 1)){
                int h = nb >> 2;
                #pragma unroll
                for (int half = 0; half < 2; half++){
                    int row = r0 + wm*64 + mt*16 + r_l + half*8;
                    float gi = half ? d[2] : d[0];
                    float gf = half ? d[3] : d[1];
                    float gg = half ? e2 : e0;
                    float go = half ? e3 : e1;
                    size_t off = (size_t)row*NH + h;
                    float cold = g_c[off];
                    float si = 1.f/(1.f + expf(-gi));
                    float sf = 1.f/(1.f + expf(-gf));
                    float so = 1.f/(1.f + expf(-go));
                    float tg = tanhf(gg);
                    float cn = sf*cold + si*tg;
                    float hn = so*tanhf(cn);
                    g_c[off] = cn;
                    __nv_bfloat16 hi, lo;
                    bf16_split(hn, hi, lo);
                    size_t a = (size_t)row*KP + NI + h;
                    Aho[a] = hi;
                    Alo[a] = lo;
                }
            }
        }
}

// Confidence PredictionNet + softmax.
__global__ __launch_bounds__(192) void conf_kernel(
        const float* __restrict__ w1, const float* __restrict__ b1,
        const float* __restrict__ w2, const float* __restrict__ b2,
        const float* __restrict__ wfc, const float* __restrict__ bfc,
        float* __restrict__ out){
    __shared__ float sw1[3600], sw2[3600], sb1[60], sb2[60], swf[60];
    __shared__ float slog[32][6];
    int tid = threadIdx.x;
    for (int i = tid; i < 3600; i += 192){ sw1[i] = w1[i]; sw2[i] = w2[i]; }
    for (int i = tid; i < 60; i += 192){ sb1[i] = b1[i]; sb2[i] = b2[i]; swf[i] = wfc[i]; }
    __syncthreads();

    int g = tid / 6, m = tid % 6;
    int b = blockIdx.x*32 + g;
    const float* x = out + ((size_t)b*NM + m)*60;
    float xr[60];
    #pragma unroll
    for (int k = 0; k < 60; k++) xr[k] = x[k];
    float y1[60];
    #pragma unroll 2
    for (int j = 0; j < 60; j++){
        float a = sb1[j];
        const float* wr = sw1 + j*60;
        #pragma unroll 4
        for (int k = 0; k < 60; k++) a = fmaf(xr[k], wr[k], a);
        y1[j] = fmaxf(a, 0.f);
    }
    float fc = bfc[0];
    #pragma unroll 2
    for (int j = 0; j < 60; j++){
        float a = sb2[j] + xr[j];
        const float* wr = sw2 + j*60;
        #pragma unroll 4
        for (int k = 0; k < 60; k++) a = fmaf(y1[k], wr[k], a);
        a = fmaxf(a, 0.f);
        fc = fmaf(a, swf[j], fc);
    }
    slog[g][m] = fc;
    __syncthreads();
    float mx = slog[g][0];
    #pragma unroll
    for (int mm = 1; mm < 6; mm++) mx = fmaxf(mx, slog[g][mm]);
    float ssum = 0.f;
    #pragma unroll
    for (int mm = 0; mm < 6; mm++) ssum += expf(slog[g][mm] - mx);
    float e = expf(fc - mx);
    out[(size_t)NB*NM*NT*2 + (size_t)b*NM + m] = e / ssum;
}

extern "C" void kernel_launch(void* const* d_in, const int* in_sizes, int n_in,
                              void* d_out, int out_size){
    (void)in_sizes; (void)n_in; (void)out_size;
    const float* traj_rel = (const float*)d_in[1];
    const float* state_h  = (const float*)d_in[2];
    const float* c0       = (const float*)d_in[3];
    const float* W_se     = (const float*)d_in[4];
    const float* b_se     = (const float*)d_in[5];
    const float* W_ih     = (const float*)d_in[6];
    const float* W_hh     = (const float*)d_in[7];
    const float* b_ih     = (const float*)d_in[8];
    const float* b_hh     = (const float*)d_in[9];
    const float* W_pred   = (const float*)d_in[10];
    const float* b_pred   = (const float*)d_in[11];
    const float* pn_w1    = (const float*)d_in[12];
    const float* pn_b1    = (const float*)d_in[13];
    const float* pn_w2    = (const float*)d_in[14];
    const float* pn_b2    = (const float*)d_in[15];
    const float* pn_wfc   = (const float*)d_in[16];
    const float* pn_bfc   = (const float*)d_in[17];
    float* out = (float*)d_out;

    cudaFuncSetAttribute(lstm_mma_kernel, cudaFuncAttributeMaxDynamicSharedMemorySize, SMEM_TOTAL);

    pack_weights<<<(NG*KP + 255)/256, 256>>>(W_ih, W_hh, b_ih, b_hh);
    init_state<<<(ROWS*NH + 255)/256, 256>>>(state_h, c0, traj_rel);
    relse_kernel<<<ROWS/8, 256>>>(W_pred, b_pred, W_se, b_se, out, -1, 0, 0);
    for (int t = 0; t < NT; t++){
        int pin = t & 1;
        lstm_mma_kernel<<<dim3(8, ROWS/128), 256, SMEM_TOTAL>>>(pin, t + 1);
        relse_kernel<<<ROWS/8, 256>>>(W_pred, b_pred, W_se, b_se, out, t, t+1, pin ^ 1);
    }
    conf_kernel<<<NB/32, 192>>>(pn_w1, pn_b1, pn_w2, pn_b2, pn_wfc, pn_bfc, out);
}

// round 7
// speedup vs baseline: 1.3456x; 1.3456x over previous
#include <cuda_runtime.h>
#include <cuda_bf16.h>
#include <cstdint>

#define NB 8192
#define NM 6
#define NH 256
#define NT 30
#define OL 20
#define NI 40        // 2*OL
#define NK 296       // NI + NH
#define KP 304       // K padded (19 chunks of 16)
#define NCH 19
#define NG 1024      // 4*NH
#define ROWS (NM*NB) // 49152
#define HIST_T (NT+OL)

// smem: per stage 4 matrices (Ah,Al,Bh,Bl), each 128 rows x 16 bf16, row stride 48B
#define STRIDE 48
#define MATB (128*STRIDE)      // 6144
#define ST (4*MATB)            // 24576
#define NSTAGE 4
#define SMEM_TOTAL (NSTAGE*ST) // 98304 -> 2 CTAs/SM

// ---------------- device state ----------------
__device__ __align__(16) __nv_bfloat16 g_Ah[2][(size_t)ROWS*KP];
__device__ __align__(16) __nv_bfloat16 g_Al[2][(size_t)ROWS*KP];
__device__ __align__(16) __nv_bfloat16 g_Bh[(size_t)NG*KP];
__device__ __align__(16) __nv_bfloat16 g_Bl[(size_t)NG*KP];
__device__ __align__(16) float g_c[(size_t)ROWS*NH];
__device__ __align__(16) float g_hist[(size_t)NM*HIST_T*NB*2];
__device__ __align__(16) unsigned char g_mask8[(size_t)ROWS*5];
__device__ __align__(16) float g_bias[NG];

// ---------------- helpers ----------------
__device__ __forceinline__ uint32_t smem_u32(const void* p){
    uint32_t a;
    asm("{ .reg .u64 t; cvta.to.shared.u64 t, %1; cvt.u32.u64 %0, t; }" : "=r"(a) : "l"(p));
    return a;
}
__device__ __forceinline__ void cp16(uint32_t dst, const void* src){
    asm volatile("cp.async.cg.shared.global [%0], [%1], 16;" :: "r"(dst), "l"(src));
}
__device__ __forceinline__ void ldsm4(uint32_t* r, uint32_t addr){
    asm volatile("ldmatrix.sync.aligned.m8n8.x4.shared.b16 {%0,%1,%2,%3}, [%4];"
        : "=r"(r[0]),"=r"(r[1]),"=r"(r[2]),"=r"(r[3]) : "r"(addr));
}
__device__ __forceinline__ void mma_bf16(float* d, const uint32_t* a, const uint32_t* b){
    asm volatile("mma.sync.aligned.m16n8k16.row.col.f32.bf16.bf16.f32 "
        "{%0,%1,%2,%3}, {%4,%5,%6,%7}, {%8,%9}, {%0,%1,%2,%3};"
        : "+f"(d[0]),"+f"(d[1]),"+f"(d[2]),"+f"(d[3])
        : "r"(a[0]),"r"(a[1]),"r"(a[2]),"r"(a[3]), "r"(b[0]),"r"(b[1]));
}
__device__ __forceinline__ void bf16_split(float x, __nv_bfloat16 &hi, __nv_bfloat16 &lo){
    hi = __float2bfloat16(x);
    lo = __float2bfloat16(x - __bfloat162float(hi));
}

// ---------------- threefry-2x32-20 (JAX partitionable) ----------------
__device__ __forceinline__ void tfr(unsigned &x0, unsigned &x1, int r){
    x0 += x1; x1 = __funnelshift_l(x1, x1, r); x1 ^= x0;
}
__device__ __forceinline__ uint2 threefry2x32(unsigned k0, unsigned k1, unsigned c0, unsigned c1){
    unsigned k2 = k0 ^ k1 ^ 0x1BD11BDAu;
    unsigned x0 = c0 + k0, x1 = c1 + k1;
    tfr(x0,x1,13); tfr(x0,x1,15); tfr(x0,x1,26); tfr(x0,x1, 6);
    x0 += k1; x1 += k2 + 1u;
    tfr(x0,x1,17); tfr(x0,x1,29); tfr(x0,x1,16); tfr(x0,x1,24);
    x0 += k2; x1 += k0 + 2u;
    tfr(x0,x1,13); tfr(x0,x1,15); tfr(x0,x1,26); tfr(x0,x1, 6);
    x0 += k0; x1 += k1 + 3u;
    tfr(x0,x1,17); tfr(x0,x1,29); tfr(x0,x1,16); tfr(x0,x1,24);
    x0 += k1; x1 += k2 + 4u;
    tfr(x0,x1,13); tfr(x0,x1,15); tfr(x0,x1,26); tfr(x0,x1, 6);
    x0 += k2; x1 += k0 + 5u;
    return make_uint2(x0, x1);
}

__device__ __forceinline__ void mask_unit(int flat, int t){
    int row = flat / 5, oct = flat % 5;
    int m = row >> 13, b = row & (NB-1);
    uint2 key = threefry2x32(0u, 42u, 0u, (unsigned)(m*NT + t));
    unsigned base = (unsigned)b*NI + (unsigned)oct*8u;
    unsigned byte = 0;
    #pragma unroll
    for (int j = 0; j < 8; j++){
        uint2 r = threefry2x32(key.x, key.y, 0u, base + (unsigned)j);
        if ((r.x ^ r.y) < 0xC0000000u) byte |= (1u << j);
    }
    g_mask8[flat] = (unsigned char)byte;
}

// Pack weights transposed+split: B[n][k], n = h*4+gate (i,f,g,o)
__global__ void pack_weights(const float* __restrict__ W_ih, const float* __restrict__ W_hh,
                             const float* __restrict__ b_ih, const float* __restrict__ b_hh){
    int idx = blockIdx.x*blockDim.x + threadIdx.x;
    if (idx < NG*KP){
        int k = idx % KP, n = idx / KP;
        int h = n >> 2, g = n & 3;
        int col = g*NH + h;
        float w = 0.f;
        if (k < NI)       w = W_ih[col*NI + k];
        else if (k < NK)  w = W_hh[col*NH + (k - NI)];
        __nv_bfloat16 hi, lo;
        bf16_split(w, hi, lo);
        g_Bh[idx] = hi;
        g_Bl[idx] = lo;
    }
    if (idx < NG){
        int h = idx >> 2, g = idx & 3;
        int col = g*NH + h;
        g_bias[idx] = b_ih[col] + b_hh[col];
    }
}

__global__ void init_state(const float* __restrict__ h0, const float* __restrict__ c0,
                           const float* __restrict__ traj){
    int idx = blockIdx.x*blockDim.x + threadIdx.x;
    if (idx < ROWS*NH){
        int h = idx % NH, row = idx / NH;
        int b = row % NB;
        float hv = h0[(size_t)b*NH + h];
        __nv_bfloat16 hi, lo;
        bf16_split(hv, hi, lo);
        size_t a = (size_t)row*KP + NI + h;
        g_Ah[0][a] = hi;
        g_Al[0][a] = lo;
        g_c[idx] = c0[idx];
    }
    if (idx < ROWS*(KP-NK)){   // zero K padding, both parities
        int p = idx % (KP-NK), row = idx / (KP-NK);
        size_t a = (size_t)row*KP + NK + p;
        g_Ah[0][a] = __float2bfloat16(0.f); g_Al[0][a] = __float2bfloat16(0.f);
        g_Ah[1][a] = __float2bfloat16(0.f); g_Al[1][a] = __float2bfloat16(0.f);
    }
    if (idx < NM*OL*NB*2){
        int dd = idx & 1;
        int rest = idx >> 1;
        int b = rest % NB; rest /= NB;
        int s = rest % OL;
        int m = rest / OL;
        g_hist[(((size_t)m*HIST_T + s)*NB + b)*2 + dd] = traj[((size_t)s*NB + b)*2 + dd];
    }
    if (idx < ROWS*5) mask_unit(idx, 0);
}

// rel head + spatial embed/dropout. One warp per (mode,batch) row.
__global__ void relse_kernel(const float* __restrict__ W_pred, const float* __restrict__ b_pred,
                             const float* __restrict__ W_se,  const float* __restrict__ b_se,
                             float* __restrict__ out, int t_out, int t_se, int hp_idx){
    __shared__ float sW[NI*41];
    __shared__ float sb[NI];
    __shared__ float swin[8][NI];
    int tid = threadIdx.x;
    int lane = tid & 31;
    int w = tid >> 5;
    for (int i = tid; i < NI*NI; i += blockDim.x){
        int j = i / NI, k = i % NI;
        sW[j*41 + k] = W_se[i];
    }
    if (tid < NI) sb[tid] = b_se[tid];
    __syncthreads();

    int row = blockIdx.x*8 + w;
    int m = row >> 13;
    int b = row & (NB-1);

    float rel0 = 0.f, rel1 = 0.f;
    if (t_out >= 0){
        const __nv_bfloat16* hh = g_Ah[hp_idx] + (size_t)row*KP + NI;
        const __nv_bfloat16* hl = g_Al[hp_idx] + (size_t)row*KP + NI;
        const float* wp = W_pred + (size_t)m*2*NH;
        float p0 = 0.f, p1 = 0.f;
        #pragma unroll
        for (int k = lane; k < NH; k += 32){
            float hv = __bfloat162float(hh[k]) + __bfloat162float(hl[k]);
            p0 = fmaf(hv, wp[k],      p0);
            p1 = fmaf(hv, wp[NH + k], p1);
        }
        #pragma unroll
        for (int off = 16; off; off >>= 1){
            p0 += __shfl_xor_sync(0xffffffffu, p0, off);
            p1 += __shfl_xor_sync(0xffffffffu, p1, off);
        }
        rel0 = p0 + b_pred[m*2 + 0];
        rel1 = p1 + b_pred[m*2 + 1];
        if (lane == 0){
            int s = t_out + OL;
            float* hp = g_hist + (((size_t)m*HIST_T + s)*NB + b)*2;
            hp[0] = rel0; hp[1] = rel1;
            float* op = out + (((size_t)b*NM + m)*NT + t_out)*2;
            op[0] = rel0; op[1] = rel1;
        }
    }

    if (t_se < NT){
        for (int k = lane; k < NI; k += 32){
            int q = k >> 1, d = k & 1;
            swin[w][k] = g_hist[(((size_t)m*HIST_T + (t_se + q))*NB + b)*2 + d];
        }
        __syncwarp();
        if (t_out >= 0 && lane == 0){
            swin[w][NI-2] = rel0;
            swin[w][NI-1] = rel1;
        }
        __syncwarp();
        int xp = t_se & 1;
        __nv_bfloat16* xh = g_Ah[xp] + (size_t)row*KP;
        __nv_bfloat16* xl = g_Al[xp] + (size_t)row*KP;
        for (int j = lane; j < NI; j += 32){
            float acc = sb[j];
            const float* wr = sW + j*41;
            #pragma unroll 8
            for (int k = 0; k < NI; k++) acc = fmaf(swin[w][k], wr[k], acc);
            acc = acc > 0.f ? acc : 0.01f*acc;
            unsigned keep = (g_mask8[row*5 + (j >> 3)] >> (j & 7)) & 1u;
            acc = keep ? acc*(1.0f/0.75f) : 0.f;
            __nv_bfloat16 hi, lo;
            bf16_split(acc, hi, lo);
            xh[j] = hi;
            xl[j] = lo;
        }
    }
}

// bf16x3 mma.sync GEMM + fused LSTM cell + next-step mask gen.
// CTA tile 128x128, 8 warps (wm 2 x wn 4; warp tile 64x32).
// K chunk 16, 4-stage cp.async pipeline, ONE __syncthreads per chunk, 2 CTAs/SM.
__global__ __launch_bounds__(256, 2) void lstm_mma_kernel(int pin, int t_next){
    extern __shared__ __align__(128) char smem[];
    const int tid = threadIdx.x;
    const int wid = tid >> 5, lane = tid & 31;
    const int wm = wid & 1, wn = wid >> 1;
    const int r0 = blockIdx.y * 128;
    const int n0 = blockIdx.x * 128;
    const uint32_t sb = smem_u32(smem);

    const __nv_bfloat16* Ah = g_Ah[pin];
    const __nv_bfloat16* Al = g_Al[pin];
    __nv_bfloat16* Aho = g_Ah[pin ^ 1];
    __nv_bfloat16* Alo = g_Al[pin ^ 1];

    float acc[4][4][4];
    #pragma unroll
    for (int i = 0; i < 4; i++)
        #pragma unroll
        for (int j = 0; j < 4; j++)
            #pragma unroll
            for (int q = 0; q < 4; q++) acc[i][j][q] = 0.f;

    auto load_stage = [&](int c){
        uint32_t base = sb + (c & 3)*ST;
        #pragma unroll
        for (int i = 0; i < 4; i++){
            int v = i*256 + tid;
            int mat = v >> 8;            // 0:Ah 1:Al 2:Bh 3:Bl
            int rr  = (v >> 1) & 127;
            int seg = v & 1;
            uint32_t dst = base + mat*MATB + rr*STRIDE + seg*16;
            const __nv_bfloat16* src;
            size_t off = (size_t)(c*16 + seg*8);
            if      (mat == 0) src = Ah   + (size_t)(r0 + rr)*KP + off;
            else if (mat == 1) src = Al   + (size_t)(r0 + rr)*KP + off;
            else if (mat == 2) src = g_Bh + (size_t)(n0 + rr)*KP + off;
            else               src = g_Bl + (size_t)(n0 + rr)*KP + off;
            cp16(dst, src);
        }
        asm volatile("cp.async.commit_group;" ::: "memory");
    };

    const int l7 = lane & 7, mi = lane >> 3;
    const uint32_t a_off = (uint32_t)((l7 + ((mi & 1) << 3))*STRIDE + ((mi >> 1) << 4));
    const uint32_t b_off = (uint32_t)((l7 + ((mi >> 1) << 3))*STRIDE + ((mi & 1) << 4));

    load_stage(0);
    load_stage(1);
    load_stage(2);

    // next-step dropout masks, hidden in pipeline slack
    {
        int flat = (blockIdx.y*gridDim.x + blockIdx.x)*blockDim.x + tid;
        if (t_next < NT && flat < ROWS*5) mask_unit(flat, t_next);
    }

    for (int c = 0; c < NCH; c++){
        asm volatile("cp.async.wait_group 2;" ::: "memory");
        __syncthreads();
        if (c + 3 < NCH) load_stage(c + 3);
        else asm volatile("cp.async.commit_group;" ::: "memory");

        uint32_t base = sb + (c & 3)*ST;
        uint32_t As  = base           + wm*64*STRIDE + a_off;
        uint32_t Als = base + MATB    + wm*64*STRIDE + a_off;
        uint32_t Bs  = base + 2*MATB  + wn*32*STRIDE + b_off;
        uint32_t Bls = base + 3*MATB  + wn*32*STRIDE + b_off;

        uint32_t ah[4][4], al[4][4];
        #pragma unroll
        for (int mt = 0; mt < 4; mt++){
            ldsm4(ah[mt], As  + mt*16*STRIDE);
            ldsm4(al[mt], Als + mt*16*STRIDE);
        }
        #pragma unroll
        for (int bt = 0; bt < 2; bt++){
            uint32_t bh4[4], bl4[4];
            ldsm4(bh4, Bs  + bt*16*STRIDE);
            ldsm4(bl4, Bls + bt*16*STRIDE);
            #pragma unroll
            for (int mt = 0; mt < 4; mt++){
                mma_bf16(acc[mt][2*bt],   ah[mt], bh4);
                mma_bf16(acc[mt][2*bt],   ah[mt], bl4);
                mma_bf16(acc[mt][2*bt],   al[mt], bh4);
                mma_bf16(acc[mt][2*bt+1], ah[mt], bh4 + 2);
                mma_bf16(acc[mt][2*bt+1], ah[mt], bl4 + 2);
                mma_bf16(acc[mt][2*bt+1], al[mt], bh4 + 2);
            }
        }
    }

    // Epilogue: fragment (mt,nt): thread owns rows r_l, r_l+8; cols 2*quad, +1.
    const int quad = lane & 3, r_l = lane >> 2;
    #pragma unroll
    for (int mt = 0; mt < 4; mt++)
        #pragma unroll
        for (int nt = 0; nt < 4; nt++){
            float* d = acc[mt][nt];
            int nb = n0 + wn*32 + nt*8 + 2*quad;
            float b0 = g_bias[nb], b1 = g_bias[nb + 1];
            d[0] += b0; d[1] += b1; d[2] += b0; d[3] += b1;
            float e0 = __shfl_xor_sync(0xffffffffu, d[0], 1);
            float e1 = __shfl_xor_sync(0xffffffffu, d[1], 1);
            float e2 = __shfl_xor_sync(0xffffffffu, d[2], 1);
            float e3 = __shfl_xor_sync(0xffffffffu, d[3], 1);
            if (!(quad & 1)){
                int h = nb >> 2;
                #pragma unroll
                for (int half = 0; half < 2; half++){
                    int row = r0 + wm*64 + mt*16 + r_l + half*8;
                    float gi = half ? d[2] : d[0];
                    float gf = half ? d[3] : d[1];
                    float gg = half ? e2 : e0;
                    float go = half ? e3 : e1;
                    size_t off = (size_t)row*NH + h;
                    float cold = g_c[off];
                    float si = 1.f/(1.f + expf(-gi));
                    float sf = 1.f/(1.f + expf(-gf));
                    float so = 1.f/(1.f + expf(-go));
                    float tg = tanhf(gg);
                    float cn = sf*cold + si*tg;
                    float hn = so*tanhf(cn);
                    g_c[off] = cn;
                    __nv_bfloat16 hi, lo;
                    bf16_split(hn, hi, lo);
                    size_t a = (size_t)row*KP + NI + h;
                    Aho[a] = hi;
                    Alo[a] = lo;
                }
            }
        }
}

// Confidence PredictionNet + softmax.
__global__ __launch_bounds__(192) void conf_kernel(
        const float* __restrict__ w1, const float* __restrict__ b1,
        const float* __restrict__ w2, const float* __restrict__ b2,
        const float* __restrict__ wfc, const float* __restrict__ bfc,
        float* __restrict__ out){
    __shared__ float sw1[3600], sw2[3600], sb1[60], sb2[60], swf[60];
    __shared__ float slog[32][6];
    int tid = threadIdx.x;
    for (int i = tid; i < 3600; i += 192){ sw1[i] = w1[i]; sw2[i] = w2[i]; }
    for (int i = tid; i < 60; i += 192){ sb1[i] = b1[i]; sb2[i] = b2[i]; swf[i] = wfc[i]; }
    __syncthreads();

    int g = tid / 6, m = tid % 6;
    int b = blockIdx.x*32 + g;
    const float* x = out + ((size_t)b*NM + m)*60;
    float xr[60];
    #pragma unroll
    for (int k = 0; k < 60; k++) xr[k] = x[k];
    float y1[60];
    #pragma unroll 2
    for (int j = 0; j < 60; j++){
        float a = sb1[j];
        const float* wr = sw1 + j*60;
        #pragma unroll 4
        for (int k = 0; k < 60; k++) a = fmaf(xr[k], wr[k], a);
        y1[j] = fmaxf(a, 0.f);
    }
    float fc = bfc[0];
    #pragma unroll 2
    for (int j = 0; j < 60; j++){
        float a = sb2[j] + xr[j];
        const float* wr = sw2 + j*60;
        #pragma unroll 4
        for (int k = 0; k < 60; k++) a = fmaf(y1[k], wr[k], a);
        a = fmaxf(a, 0.f);
        fc = fmaf(a, swf[j], fc);
    }
    slog[g][m] = fc;
    __syncthreads();
    float mx = slog[g][0];
    #pragma unroll
    for (int mm = 1; mm < 6; mm++) mx = fmaxf(mx, slog[g][mm]);
    float ssum = 0.f;
    #pragma unroll
    for (int mm = 0; mm < 6; mm++) ssum += expf(slog[g][mm] - mx);
    float e = expf(fc - mx);
    out[(size_t)NB*NM*NT*2 + (size_t)b*NM + m] = e / ssum;
}

extern "C" void kernel_launch(void* const* d_in, const int* in_sizes, int n_in,
                              void* d_out, int out_size){
    (void)in_sizes; (void)n_in; (void)out_size;
    const float* traj_rel = (const float*)d_in[1];
    const float* state_h  = (const float*)d_in[2];
    const float* c0       = (const float*)d_in[3];
    const float* W_se     = (const float*)d_in[4];
    const float* b_se     = (const float*)d_in[5];
    const float* W_ih     = (const float*)d_in[6];
    const float* W_hh     = (const float*)d_in[7];
    const float* b_ih     = (const float*)d_in[8];
    const float* b_hh     = (const float*)d_in[9];
    const float* W_pred   = (const float*)d_in[10];
    const float* b_pred   = (const float*)d_in[11];
    const float* pn_w1    = (const float*)d_in[12];
    const float* pn_b1    = (const float*)d_in[13];
    const float* pn_w2    = (const float*)d_in[14];
    const float* pn_b2    = (const float*)d_in[15];
    const float* pn_wfc   = (const float*)d_in[16];
    const float* pn_bfc   = (const float*)d_in[17];
    float* out = (float*)d_out;

    cudaFuncSetAttribute(lstm_mma_kernel, cudaFuncAttributeMaxDynamicSharedMemorySize, SMEM_TOTAL);

    pack_weights<<<(NG*KP + 255)/256, 256>>>(W_ih, W_hh, b_ih, b_hh);
    init_state<<<(ROWS*NH + 255)/256, 256>>>(state_h, c0, traj_rel);
    relse_kernel<<<ROWS/8, 256>>>(W_pred, b_pred, W_se, b_se, out, -1, 0, 0);
    for (int t = 0; t < NT; t++){
        int pin = t & 1;
        lstm_mma_kernel<<<dim3(8, ROWS/128), 256, SMEM_TOTAL>>>(pin, t + 1);
        relse_kernel<<<ROWS/8, 256>>>(W_pred, b_pred, W_se, b_se, out, t, t+1, pin ^ 1);
    }
    conf_kernel<<<NB/32, 192>>>(pn_w1, pn_b1, pn_w2, pn_b2, pn_wfc, pn_bfc, out);
}